// round 1
// baseline (speedup 1.0000x reference)
#include <cuda_runtime.h>

// Problem constants
// B=4, C=256, H=W=32, N=1024, heads=8, dk=32, KV len = 3N = 3072
#define CN (256 * 1024)   // one [C,N] matrix in floats

// Scratch (allocation-free rule: __device__ globals)
__device__ float g_Q[4 * 256 * 1024];        // [B][C][N]   (C = h*32+d)
__device__ float g_K[12 * 256 * 1024];       // [B][3][C][N]
__device__ float g_V[12 * 256 * 1024];       // [B][3][C][N]
__device__ float g_att[4 * 256 * 1024];      // [B][C][N]

// ---------------------------------------------------------------------------
// SGEMM body: out[m0:+128, n0:+128] = W[256x256] @ (scale * X[256x1024]) + bias
// 256 threads, 8x8 per thread, K-step 8.
// ---------------------------------------------------------------------------
__device__ __forceinline__ void sgemm_256(const float* __restrict__ W,
                                          const float* __restrict__ X,
                                          const float* __restrict__ bias,
                                          float scale,
                                          float* __restrict__ out,
                                          int m0, int n0)
{
    __shared__ float As[8][128];   // As[k][o]
    __shared__ float Bs[8][128];   // Bs[k][n]

    const int t  = threadIdx.x;
    const int tx = t & 15;         // n-tile position
    const int ty = t >> 4;         // m-tile position
    const int arow = t >> 1, acol = (t & 1) * 4;
    const int brow = t >> 5, bcol = (t & 31) * 4;

    float acc[8][8];
#pragma unroll
    for (int i = 0; i < 8; i++)
#pragma unroll
        for (int j = 0; j < 8; j++) acc[i][j] = 0.f;

    for (int k0 = 0; k0 < 256; k0 += 8) {
        float4 av = *(const float4*)(W + (m0 + arow) * 256 + k0 + acol);
        float4 bv = *(const float4*)(X + (k0 + brow) * 1024 + n0 + bcol);
        __syncthreads();
        As[acol + 0][arow] = av.x;
        As[acol + 1][arow] = av.y;
        As[acol + 2][arow] = av.z;
        As[acol + 3][arow] = av.w;
        bv.x *= scale; bv.y *= scale; bv.z *= scale; bv.w *= scale;
        *(float4*)&Bs[brow][bcol] = bv;
        __syncthreads();
#pragma unroll
        for (int k = 0; k < 8; k++) {
            float a[8], b[8];
            *(float4*)&a[0] = *(float4*)&As[k][ty * 8];
            *(float4*)&a[4] = *(float4*)&As[k][ty * 8 + 4];
            *(float4*)&b[0] = *(float4*)&Bs[k][tx * 8];
            *(float4*)&b[4] = *(float4*)&Bs[k][tx * 8 + 4];
#pragma unroll
            for (int i = 0; i < 8; i++)
#pragma unroll
                for (int j = 0; j < 8; j++)
                    acc[i][j] = fmaf(a[i], b[j], acc[i][j]);
        }
    }

#pragma unroll
    for (int i = 0; i < 8; i++) {
        float bi = bias[m0 + ty * 8 + i];
        float4 o0 = make_float4(acc[i][0] + bi, acc[i][1] + bi,
                                acc[i][2] + bi, acc[i][3] + bi);
        float4 o1 = make_float4(acc[i][4] + bi, acc[i][5] + bi,
                                acc[i][6] + bi, acc[i][7] + bi);
        float* orow = out + (m0 + ty * 8 + i) * 1024 + n0 + tx * 8;
        *(float4*)orow = o0;
        *(float4*)(orow + 4) = o1;
    }
}

// QKV projections. grid = (8 n-tiles, 2 m-tiles, 28); z -> (b, which-of-7)
// which: 0 = Q (stream 0), 1..3 = K stream s, 4..6 = V stream s
__global__ void __launch_bounds__(256)
gemm_qkv_kernel(const float* __restrict__ x0, const float* __restrict__ x1,
                const float* __restrict__ x2,
                const float* __restrict__ g0, const float* __restrict__ g1,
                const float* __restrict__ g2,
                const float* __restrict__ Wq, const float* __restrict__ bq,
                const float* __restrict__ Wk, const float* __restrict__ bk,
                const float* __restrict__ Wv, const float* __restrict__ bv)
{
    const int z = blockIdx.z;
    const int b = z / 7;
    const int r = z % 7;

    const float* W;
    const float* bias;
    float* out;
    int s;
    if (r == 0)      { s = 0;     W = Wq; bias = bq; out = g_Q + b * CN; }
    else if (r <= 3) { s = r - 1; W = Wk; bias = bk; out = g_K + (b * 3 + s) * CN; }
    else             { s = r - 4; W = Wv; bias = bv; out = g_V + (b * 3 + s) * CN; }

    const float* X = (s == 0 ? x0 : (s == 1 ? x1 : x2)) + b * CN;
    const float scale = (s == 0 ? g0 : (s == 1 ? g1 : g2))[0];

    sgemm_256(W, X, bias, scale, out, blockIdx.y * 128, blockIdx.x * 128);
}

// Output projection. grid = (8, 2, 4)
__global__ void __launch_bounds__(256)
gemm_out_kernel(const float* __restrict__ Wo, const float* __restrict__ bo,
                float* __restrict__ outp)
{
    const int b = blockIdx.z;
    sgemm_256(Wo, g_att + b * CN, bo, 1.0f, outp + b * CN,
              blockIdx.y * 128, blockIdx.x * 128);
}

// ---------------------------------------------------------------------------
// Flash attention: grid = (16 q-tiles, 8 heads, 4 batch), 256 threads.
// Q tile 64, K tile 64, dk = 32, KV length 3072 (48 tiles).
// Thread (tx,ty): S microtile = rows ty*4..+3 x cols tx*4..+3
//                 O microtile = rows ty*4..+3 x dims tx*2..+1
// ---------------------------------------------------------------------------
__global__ void __launch_bounds__(256)
attn_kernel()
{
    const int b  = blockIdx.z;
    const int h  = blockIdx.y;
    const int q0 = blockIdx.x * 64;

    __shared__ float Qs[32][64];    // [d][q], pre-scaled by 1/sqrt(dk)
    __shared__ float Ks[32][64];    // [d][k]
    __shared__ float Vs[32][65];    // [d][k], pad -> conflict-free column reads
    __shared__ float Ps[64][65];    // [q][k] softmax numerators

    const int t  = threadIdx.x;
    const int tx = t & 15;
    const int ty = t >> 4;
    const float qscale = 0.1767766953f;   // 1/sqrt(32)

    // Load Q tile (coalesced, 2 float4 per thread), fold in the scale
    {
        const float* Qg = g_Q + (b * 256 + h * 32) * 1024 + q0;
#pragma unroll
        for (int u = 0; u < 2; u++) {
            int li = t * 2 + u;
            int d = li >> 4, qo = (li & 15) * 4;
            float4 v = *(const float4*)(Qg + d * 1024 + qo);
            v.x *= qscale; v.y *= qscale; v.z *= qscale; v.w *= qscale;
            *(float4*)&Qs[d][qo] = v;
        }
    }

    float m[4], l[4], o[4][2];
#pragma unroll
    for (int i = 0; i < 4; i++) {
        m[i] = -1e30f; l[i] = 0.f; o[i][0] = 0.f; o[i][1] = 0.f;
    }

    for (int kt = 0; kt < 48; kt++) {
        const int s  = kt >> 4;
        const int n0 = (kt & 15) * 64;
        const float* Kg = g_K + ((b * 3 + s) * 256 + h * 32) * 1024 + n0;
        const float* Vg = g_V + ((b * 3 + s) * 256 + h * 32) * 1024 + n0;

        __syncthreads();   // protect Ks/Vs/Ps from previous iteration readers
#pragma unroll
        for (int u = 0; u < 2; u++) {
            int li = t * 2 + u;
            int d = li >> 4, qo = (li & 15) * 4;
            float4 kv = *(const float4*)(Kg + d * 1024 + qo);
            *(float4*)&Ks[d][qo] = kv;
            float4 vv = *(const float4*)(Vg + d * 1024 + qo);
            Vs[d][qo + 0] = vv.x; Vs[d][qo + 1] = vv.y;
            Vs[d][qo + 2] = vv.z; Vs[d][qo + 3] = vv.w;
        }
        __syncthreads();

        // S = (Q^T K) for this tile, 4x4 per thread
        float sacc[4][4];
#pragma unroll
        for (int i = 0; i < 4; i++)
#pragma unroll
            for (int j = 0; j < 4; j++) sacc[i][j] = 0.f;

#pragma unroll
        for (int d = 0; d < 32; d++) {
            float4 aq = *(float4*)&Qs[d][ty * 4];
            float4 bk = *(float4*)&Ks[d][tx * 4];
            float a[4] = {aq.x, aq.y, aq.z, aq.w};
            float c[4] = {bk.x, bk.y, bk.z, bk.w};
#pragma unroll
            for (int i = 0; i < 4; i++)
#pragma unroll
                for (int j = 0; j < 4; j++)
                    sacc[i][j] = fmaf(a[i], c[j], sacc[i][j]);
        }

        // Online softmax (per-row stats across 16 tx lanes via butterfly shfl;
        // lanes 0..15 / 16..31 are distinct ty so xor<=8 stays in-group)
#pragma unroll
        for (int i = 0; i < 4; i++) {
            float mx = fmaxf(fmaxf(sacc[i][0], sacc[i][1]),
                             fmaxf(sacc[i][2], sacc[i][3]));
#pragma unroll
            for (int w = 1; w < 16; w <<= 1)
                mx = fmaxf(mx, __shfl_xor_sync(0xffffffffu, mx, w));
            float mnew = fmaxf(m[i], mx);
            float ratio = __expf(m[i] - mnew);
            float rs = 0.f;
#pragma unroll
            for (int j = 0; j < 4; j++) {
                float p = __expf(sacc[i][j] - mnew);
                Ps[ty * 4 + i][tx * 4 + j] = p;
                rs += p;
            }
#pragma unroll
            for (int w = 1; w < 16; w <<= 1)
                rs += __shfl_xor_sync(0xffffffffu, rs, w);
            l[i] = l[i] * ratio + rs;
            m[i] = mnew;
            o[i][0] *= ratio;
            o[i][1] *= ratio;
        }
        __syncthreads();

        // O += P @ V^T  (thread owns 4 q-rows x 2 dims)
        const int d0 = tx * 2;
#pragma unroll 4
        for (int k = 0; k < 64; k++) {
            float v0 = Vs[d0][k];
            float v1 = Vs[d0 + 1][k];
#pragma unroll
            for (int i = 0; i < 4; i++) {
                float p = Ps[ty * 4 + i][k];
                o[i][0] = fmaf(p, v0, o[i][0]);
                o[i][1] = fmaf(p, v1, o[i][1]);
            }
        }
    }

    // Normalize and write out in [B][C][N] layout (C = h*32 + d)
#pragma unroll
    for (int i = 0; i < 4; i++) {
        float inv = 1.0f / l[i];
        int q = q0 + ty * 4 + i;
        g_att[(b * 256 + h * 32 + tx * 2 + 0) * 1024 + q] = o[i][0] * inv;
        g_att[(b * 256 + h * 32 + tx * 2 + 1) * 1024 + q] = o[i][1] * inv;
    }
}

// ---------------------------------------------------------------------------
extern "C" void kernel_launch(void* const* d_in, const int* in_sizes, int n_in,
                              void* d_out, int out_size)
{
    const float* x0 = (const float*)d_in[0];
    const float* x1 = (const float*)d_in[1];
    const float* x2 = (const float*)d_in[2];
    const float* g0 = (const float*)d_in[3];
    const float* g1 = (const float*)d_in[4];
    const float* g2 = (const float*)d_in[5];
    const float* Wq = (const float*)d_in[6];
    const float* bq = (const float*)d_in[7];
    const float* Wk = (const float*)d_in[8];
    const float* bk = (const float*)d_in[9];
    const float* Wv = (const float*)d_in[10];
    const float* bv = (const float*)d_in[11];
    const float* Wo = (const float*)d_in[12];
    const float* bo = (const float*)d_in[13];
    float* outp = (float*)d_out;

    dim3 gq(8, 2, 28);   // n-tiles, m-tiles, (b,which)
    gemm_qkv_kernel<<<gq, 256>>>(x0, x1, x2, g0, g1, g2,
                                 Wq, bq, Wk, bk, Wv, bv);

    dim3 ga(16, 8, 4);   // q-tiles, heads, batch
    attn_kernel<<<ga, 256>>>();

    dim3 go(8, 2, 4);
    gemm_out_kernel<<<go, 256>>>(Wo, bo, outp);
}

// round 2
// speedup vs baseline: 1.0215x; 1.0215x over previous
#include <cuda_runtime.h>

// B=4, C=256, N=1024, heads=8, dk=32, KV len = 3072
#define CN (256 * 1024)

__device__ float g_Q[4 * 256 * 1024];        // [B][C][N]
__device__ float g_K[12 * 256 * 1024];       // [B][3][C][N]
__device__ float g_V[12 * 256 * 1024];       // [B][3][C][N]
__device__ float g_att[4 * 256 * 1024];      // [B][C][N]

typedef unsigned long long u64;

// Packed fp32x2 helpers (sm_100+ PTX; FFMA2 doubles fp32 rate per issue slot)
__device__ __forceinline__ u64 ffma2(u64 a, u64 b, u64 c) {
    u64 d; asm("fma.rn.f32x2 %0, %1, %2, %3;" : "=l"(d) : "l"(a), "l"(b), "l"(c));
    return d;
}
__device__ __forceinline__ u64 fmul2(u64 a, u64 b) {
    u64 d; asm("mul.rn.f32x2 %0, %1, %2;" : "=l"(d) : "l"(a), "l"(b));
    return d;
}
__device__ __forceinline__ u64 pack2(float lo, float hi) {
    u64 r; asm("mov.b64 %0, {%1, %2};" : "=l"(r) : "f"(lo), "f"(hi));
    return r;
}
__device__ __forceinline__ float2 unpack2(u64 v) {
    float2 r; asm("mov.b64 {%0, %1}, %2;" : "=f"(r.x), "=f"(r.y) : "l"(v));
    return r;
}

// ---------------------------------------------------------------------------
// SGEMM: out[m0:+128, n0:+128] = W[256x256] @ (scale*X[256x1024]) + bias
// 256 threads, 8x8 per thread via FFMA2 (8 rows x 4 col-pairs).
// A staged duplicated in SMEM so broadcast-pairs come straight from LDS.128.
// ---------------------------------------------------------------------------
__device__ __forceinline__ void sgemm_256(const float* __restrict__ W,
                                          const float* __restrict__ X,
                                          const float* __restrict__ bias,
                                          float scale,
                                          float* __restrict__ out,
                                          int m0, int n0)
{
    __shared__ float As2[8][256];   // As2[k][2o], [2o+1] = W[m0+o][k0+k]
    __shared__ float Bs[8][128];    // Bs[k][n]

    const int t  = threadIdx.x;
    const int tx = t & 15;
    const int ty = t >> 4;
    const int arow = t >> 1, acol = (t & 1) * 4;
    const int brow = t >> 5, bcol = (t & 31) * 4;

    u64 acc[8][4];
#pragma unroll
    for (int i = 0; i < 8; i++)
#pragma unroll
        for (int j = 0; j < 4; j++) acc[i][j] = 0ull;

    for (int k0 = 0; k0 < 256; k0 += 8) {
        float4 av = *(const float4*)(W + (m0 + arow) * 256 + k0 + acol);
        float4 bv = *(const float4*)(X + (k0 + brow) * 1024 + n0 + bcol);
        __syncthreads();
        *(float2*)&As2[acol + 0][2 * arow] = make_float2(av.x, av.x);
        *(float2*)&As2[acol + 1][2 * arow] = make_float2(av.y, av.y);
        *(float2*)&As2[acol + 2][2 * arow] = make_float2(av.z, av.z);
        *(float2*)&As2[acol + 3][2 * arow] = make_float2(av.w, av.w);
        bv.x *= scale; bv.y *= scale; bv.z *= scale; bv.w *= scale;
        *(float4*)&Bs[brow][bcol] = bv;
        __syncthreads();
#pragma unroll
        for (int k = 0; k < 8; k++) {
            ulonglong2 a0 = *(const ulonglong2*)&As2[k][16 * ty];
            ulonglong2 a1 = *(const ulonglong2*)&As2[k][16 * ty + 4];
            ulonglong2 a2 = *(const ulonglong2*)&As2[k][16 * ty + 8];
            ulonglong2 a3 = *(const ulonglong2*)&As2[k][16 * ty + 12];
            ulonglong2 b0 = *(const ulonglong2*)&Bs[k][tx * 8];
            ulonglong2 b1 = *(const ulonglong2*)&Bs[k][tx * 8 + 4];
            u64 a[8] = {a0.x, a0.y, a1.x, a1.y, a2.x, a2.y, a3.x, a3.y};
            u64 b[4] = {b0.x, b0.y, b1.x, b1.y};
#pragma unroll
            for (int i = 0; i < 8; i++)
#pragma unroll
                for (int j = 0; j < 4; j++)
                    acc[i][j] = ffma2(a[i], b[j], acc[i][j]);
        }
    }

#pragma unroll
    for (int i = 0; i < 8; i++) {
        float bi = bias[m0 + ty * 8 + i];
        float2 p0 = unpack2(acc[i][0]);
        float2 p1 = unpack2(acc[i][1]);
        float2 p2 = unpack2(acc[i][2]);
        float2 p3 = unpack2(acc[i][3]);
        float* orow = out + (m0 + ty * 8 + i) * 1024 + n0 + tx * 8;
        *(float4*)orow       = make_float4(p0.x + bi, p0.y + bi, p1.x + bi, p1.y + bi);
        *(float4*)(orow + 4) = make_float4(p2.x + bi, p2.y + bi, p3.x + bi, p3.y + bi);
    }
}

// QKV projections. grid = (8, 2, 28); z -> (b, which-of-7)
__global__ void __launch_bounds__(256)
gemm_qkv_kernel(const float* __restrict__ x0, const float* __restrict__ x1,
                const float* __restrict__ x2,
                const float* __restrict__ g0, const float* __restrict__ g1,
                const float* __restrict__ g2,
                const float* __restrict__ Wq, const float* __restrict__ bq,
                const float* __restrict__ Wk, const float* __restrict__ bk,
                const float* __restrict__ Wv, const float* __restrict__ bv)
{
    const int z = blockIdx.z;
    const int b = z / 7;
    const int r = z % 7;

    const float* W;
    const float* bias;
    float* out;
    int s;
    if (r == 0)      { s = 0;     W = Wq; bias = bq; out = g_Q + b * CN; }
    else if (r <= 3) { s = r - 1; W = Wk; bias = bk; out = g_K + (b * 3 + s) * CN; }
    else             { s = r - 4; W = Wv; bias = bv; out = g_V + (b * 3 + s) * CN; }

    const float* X = (s == 0 ? x0 : (s == 1 ? x1 : x2)) + b * CN;
    const float scale = (s == 0 ? g0 : (s == 1 ? g1 : g2))[0];

    sgemm_256(W, X, bias, scale, out, blockIdx.y * 128, blockIdx.x * 128);
}

// Output projection. grid = (8, 2, 4)
__global__ void __launch_bounds__(256)
gemm_out_kernel(const float* __restrict__ Wo, const float* __restrict__ bo,
                float* __restrict__ outp)
{
    const int b = blockIdx.z;
    sgemm_256(Wo, g_att + b * CN, bo, 1.0f, outp + b * CN,
              blockIdx.y * 128, blockIdx.x * 128);
}

// ---------------------------------------------------------------------------
// Flash attention: grid = (16 q-tiles, 8 heads, 4 batch), 256 threads.
// Q tile 64, K tile 64, dk=32, KV=3072 (48 tiles). All math in FFMA2.
// Thread (tx,ty): S microtile rows ty*4..+3 x cols tx*4..+3
//                 O microtile rows ty*4..+3 x dims tx*2..+1 (k-paired partial sums)
// ---------------------------------------------------------------------------
__global__ void __launch_bounds__(256)
attn_kernel()
{
    const int b  = blockIdx.z;
    const int h  = blockIdx.y;
    const int q0 = blockIdx.x * 64;

    __shared__ float Qs2[32][132];  // dup pairs: Qs2[d][2q],[2q+1] = Q[d][q]*qscale
    __shared__ float Ks[32][64];    // [d][k]
    __shared__ float Vs[32][66];    // [d][k] (pad 66: rows 8B-aligned)
    __shared__ float Ps[64][68];    // [q][k] softmax numerators (pad 68)

    const int t  = threadIdx.x;
    const int tx = t & 15;
    const int ty = t >> 4;
    const float qscale = 0.1767766953f;   // 1/sqrt(32)

    // Load Q tile duplicated (broadcast pairs ready for FFMA2)
    {
        const float* Qg = g_Q + (b * 256 + h * 32) * 1024 + q0;
#pragma unroll
        for (int u = 0; u < 2; u++) {
            int li = t * 2 + u;
            int d = li >> 4, qo = (li & 15) * 4;
            float4 v = *(const float4*)(Qg + d * 1024 + qo);
            v.x *= qscale; v.y *= qscale; v.z *= qscale; v.w *= qscale;
            *(float4*)&Qs2[d][2 * qo]     = make_float4(v.x, v.x, v.y, v.y);
            *(float4*)&Qs2[d][2 * qo + 4] = make_float4(v.z, v.z, v.w, v.w);
        }
    }

    float m[4], l[4];
    u64 o2[4][2];
#pragma unroll
    for (int i = 0; i < 4; i++) {
        m[i] = -1e30f; l[i] = 0.f; o2[i][0] = 0ull; o2[i][1] = 0ull;
    }

    for (int kt = 0; kt < 48; kt++) {
        const int s  = kt >> 4;
        const int n0 = (kt & 15) * 64;
        const float* Kg = g_K + ((b * 3 + s) * 256 + h * 32) * 1024 + n0;
        const float* Vg = g_V + ((b * 3 + s) * 256 + h * 32) * 1024 + n0;

        __syncthreads();   // protect Ks/Vs/Ps from previous iteration readers
#pragma unroll
        for (int u = 0; u < 2; u++) {
            int li = t * 2 + u;
            int d = li >> 4, qo = (li & 15) * 4;
            float4 kv = *(const float4*)(Kg + d * 1024 + qo);
            *(float4*)&Ks[d][qo] = kv;
            float4 vv = *(const float4*)(Vg + d * 1024 + qo);
            *(float2*)&Vs[d][qo]     = make_float2(vv.x, vv.y);
            *(float2*)&Vs[d][qo + 2] = make_float2(vv.z, vv.w);
        }
        __syncthreads();

        // S = Q^T K, 4 rows x 2 col-pairs per thread in FFMA2
        u64 s2[4][2];
#pragma unroll
        for (int i = 0; i < 4; i++) { s2[i][0] = 0ull; s2[i][1] = 0ull; }

#pragma unroll
        for (int d = 0; d < 32; d++) {
            ulonglong2 qa = *(const ulonglong2*)&Qs2[d][8 * ty];      // rows 0,1 dup
            ulonglong2 qb = *(const ulonglong2*)&Qs2[d][8 * ty + 4];  // rows 2,3 dup
            ulonglong2 kk = *(const ulonglong2*)&Ks[d][tx * 4];       // col pairs
            s2[0][0] = ffma2(qa.x, kk.x, s2[0][0]);
            s2[0][1] = ffma2(qa.x, kk.y, s2[0][1]);
            s2[1][0] = ffma2(qa.y, kk.x, s2[1][0]);
            s2[1][1] = ffma2(qa.y, kk.y, s2[1][1]);
            s2[2][0] = ffma2(qb.x, kk.x, s2[2][0]);
            s2[2][1] = ffma2(qb.x, kk.y, s2[2][1]);
            s2[3][0] = ffma2(qb.y, kk.x, s2[3][0]);
            s2[3][1] = ffma2(qb.y, kk.y, s2[3][1]);
        }

        // Online softmax (row stats across 16 tx lanes via butterfly shfl)
#pragma unroll
        for (int i = 0; i < 4; i++) {
            float2 c0 = unpack2(s2[i][0]);
            float2 c1 = unpack2(s2[i][1]);
            float sc[4] = {c0.x, c0.y, c1.x, c1.y};
            float mx = fmaxf(fmaxf(sc[0], sc[1]), fmaxf(sc[2], sc[3]));
#pragma unroll
            for (int w = 1; w < 16; w <<= 1)
                mx = fmaxf(mx, __shfl_xor_sync(0xffffffffu, mx, w));
            float mnew = fmaxf(m[i], mx);
            float ratio = __expf(m[i] - mnew);
            float p0 = __expf(sc[0] - mnew);
            float p1 = __expf(sc[1] - mnew);
            float p2 = __expf(sc[2] - mnew);
            float p3 = __expf(sc[3] - mnew);
            *(float4*)&Ps[ty * 4 + i][tx * 4] = make_float4(p0, p1, p2, p3);
            float rs = (p0 + p1) + (p2 + p3);
#pragma unroll
            for (int w = 1; w < 16; w <<= 1)
                rs += __shfl_xor_sync(0xffffffffu, rs, w);
            l[i] = l[i] * ratio + rs;
            m[i] = mnew;
            u64 rr = pack2(ratio, ratio);
            o2[i][0] = fmul2(o2[i][0], rr);
            o2[i][1] = fmul2(o2[i][1], rr);
        }
        __syncthreads();

        // O += P @ V^T, k processed in pairs (FFMA2 partial sums)
        const int d0 = tx * 2;
#pragma unroll
        for (int k = 0; k < 64; k += 2) {
            u64 v0 = *(const u64*)&Vs[d0][k];
            u64 v1 = *(const u64*)&Vs[d0 + 1][k];
#pragma unroll
            for (int i = 0; i < 4; i++) {
                u64 p = *(const u64*)&Ps[ty * 4 + i][k];
                o2[i][0] = ffma2(p, v0, o2[i][0]);
                o2[i][1] = ffma2(p, v1, o2[i][1]);
            }
        }
    }

    // Merge k-parity partials, normalize, write [B][C][N] (C = h*32 + d)
#pragma unroll
    for (int i = 0; i < 4; i++) {
        float inv = 1.0f / l[i];
        int q = q0 + ty * 4 + i;
        float2 a0 = unpack2(o2[i][0]);
        float2 a1 = unpack2(o2[i][1]);
        g_att[(b * 256 + h * 32 + tx * 2 + 0) * 1024 + q] = (a0.x + a0.y) * inv;
        g_att[(b * 256 + h * 32 + tx * 2 + 1) * 1024 + q] = (a1.x + a1.y) * inv;
    }
}

// ---------------------------------------------------------------------------
extern "C" void kernel_launch(void* const* d_in, const int* in_sizes, int n_in,
                              void* d_out, int out_size)
{
    const float* x0 = (const float*)d_in[0];
    const float* x1 = (const float*)d_in[1];
    const float* x2 = (const float*)d_in[2];
    const float* g0 = (const float*)d_in[3];
    const float* g1 = (const float*)d_in[4];
    const float* g2 = (const float*)d_in[5];
    const float* Wq = (const float*)d_in[6];
    const float* bq = (const float*)d_in[7];
    const float* Wk = (const float*)d_in[8];
    const float* bk = (const float*)d_in[9];
    const float* Wv = (const float*)d_in[10];
    const float* bv = (const float*)d_in[11];
    const float* Wo = (const float*)d_in[12];
    const float* bo = (const float*)d_in[13];
    float* outp = (float*)d_out;

    dim3 gq(8, 2, 28);
    gemm_qkv_kernel<<<gq, 256>>>(x0, x1, x2, g0, g1, g2,
                                 Wq, bq, Wk, bk, Wv, bv);

    dim3 ga(16, 8, 4);
    attn_kernel<<<ga, 256>>>();

    dim3 go(8, 2, 4);
    gemm_out_kernel<<<go, 256>>>(Wo, bo, outp);
}